// round 16
// baseline (speedup 1.0000x reference)
#include <cuda_runtime.h>
#include <math.h>

// Problem constants (shapes fixed by the dataset)
#define NN 50000
#define NE 800000
#define D0 64   // x features
#define D1 96   // hidden
#define D2 64   // out

#define GRID 592    // 4 blocks/SM * 148 SMs
#define NT   256    // threads per block

// ---------------- scratch (device globals: no allocation allowed) ----------
__device__ int      g_is64;
__device__ int      g_csr[NE];
__device__ int      g_cnt[NN];
__device__ int      g_row[NN + 1];
__device__ int      g_cur[NN];
__device__ float    g_dis[NN];
__device__ int      g_bsum[GRID];
__device__ int      g_bpre[GRID];
__device__ unsigned g_barrier_ctr;   // monotonic across launches (replay-safe)
__device__ unsigned g_steal[2];      // work-steal: fused-tile, agg2
__device__ float    g_hs2[NN * D2];  // (relu(zW1+b1) W2) * dis[row]

__device__ __forceinline__ float act_relu(float v)    { return fmaxf(v, 0.0f); }
__device__ __forceinline__ float act_sigmoid(float v) { return 1.0f / (1.0f + expf(-v)); }

// ---------------- software grid barrier ------------------------------------
__device__ __forceinline__ void gbar() {
    __threadfence();
    __syncthreads();
    if (threadIdx.x == 0) {
        unsigned old = atomicAdd(&g_barrier_ctr, 1u);
        unsigned target = (old / GRID) * GRID + GRID;
        while ((int)(*(volatile unsigned*)&g_barrier_ctr - target) < 0)
            __nanosleep(64);
        __threadfence();
    }
    __syncthreads();
}

// ---------------- z gather: one node -> smem row ----------------------------
// z_i = dis_i * ( dis_i*x_i + sum_e dis_src*x_src ), 64 floats via float2/lane
__device__ __forceinline__ void aggx_to_smem(int node, const float2* __restrict__ X2,
                                             float* __restrict__ sRow, int lane) {
    constexpr int C2 = D0 / 2;   // 32, all lanes active
    int beg = g_row[node], end = g_row[node + 1];
    float di = g_dis[node];
    float2 xv = X2[node * C2 + lane];
    float2 acc = make_float2(xv.x * di, xv.y * di);   // self: dis_i * x_i

    int j = beg;
    for (; j + 4 <= end; j += 4) {
        int s0 = g_csr[j + 0], s1 = g_csr[j + 1];
        int s2 = g_csr[j + 2], s3 = g_csr[j + 3];
        float d0 = g_dis[s0], d1 = g_dis[s1], d2 = g_dis[s2], d3 = g_dis[s3];
        float2 v0 = X2[s0 * C2 + lane];
        float2 v1 = X2[s1 * C2 + lane];
        float2 v2 = X2[s2 * C2 + lane];
        float2 v3 = X2[s3 * C2 + lane];
        acc.x = fmaf(v0.x, d0, fmaf(v1.x, d1, fmaf(v2.x, d2, fmaf(v3.x, d3, acc.x))));
        acc.y = fmaf(v0.y, d0, fmaf(v1.y, d1, fmaf(v2.y, d2, fmaf(v3.y, d3, acc.y))));
    }
    for (; j < end; j++) {
        int s0 = g_csr[j];
        float d0 = g_dis[s0];
        float2 v = X2[s0 * C2 + lane];
        acc.x = fmaf(v.x, d0, acc.x);
        acc.y = fmaf(v.y, d0, acc.y);
    }
    ((float2*)sRow)[lane] = make_float2(di * acc.x, di * acc.y);
}

// Layer-2 agg on PRE-SCALED hs2 (64f):
//   out_i = sigmoid( dis_i * ( hs2_i + sum_e hs2_src ) + b2 )
__device__ __forceinline__ void agg2_node(int node, const float2* __restrict__ H2,
                                          const float* __restrict__ b,
                                          float* __restrict__ OUT, int lane) {
    constexpr int C2 = D2 / 2;   // 32
    int beg = g_row[node], end = g_row[node + 1];
    float2 acc = H2[node * C2 + lane];
    int j = beg;
    for (; j + 4 <= end; j += 4) {
        int s0 = g_csr[j + 0], s1 = g_csr[j + 1];
        int s2 = g_csr[j + 2], s3 = g_csr[j + 3];
        float2 v0 = H2[s0 * C2 + lane];
        float2 v1 = H2[s1 * C2 + lane];
        float2 v2 = H2[s2 * C2 + lane];
        float2 v3 = H2[s3 * C2 + lane];
        acc.x += (v0.x + v1.x) + (v2.x + v3.x);
        acc.y += (v0.y + v1.y) + (v2.y + v3.y);
    }
    for (; j < end; j++) {
        int s0 = g_csr[j];
        float2 v = H2[s0 * C2 + lane];
        acc.x += v.x; acc.y += v.y;
    }
    float d = g_dis[node];
    float2 bb = ((const float2*)b)[lane];
    float2 o;
    o.x = act_sigmoid(fmaf(d, acc.x, bb.x));
    o.y = act_sigmoid(fmaf(d, acc.y, bb.y));
    ((float2*)OUT)[node * C2 + lane] = o;
}

// ---------------- the single fused persistent kernel -----------------------
// smem: sW1 24KB + sW2 24KB + sT 6KB + b1 384B (+scan overlaid on sT)
// = 55.7KB raw -> <=56KB granule; x4 blocks = 224KB <= 228KB. Regs <=64.
__global__ void __launch_bounds__(NT, 4)
k_fused(const float* __restrict__ x, const void* __restrict__ ep,
        const float* __restrict__ W1, const float* __restrict__ b1,
        const float* __restrict__ W2, const float* __restrict__ b2,
        float* __restrict__ out) {
    __shared__ __align__(16) float sW1[D0 * D1];   // 24576 B
    __shared__ __align__(16) float sW2[D1 * D2];   // 24576 B
    __shared__ __align__(16) float sT [16 * D1];   // 6144 B: z tile 16x64 / h tile 16x96
    __shared__ float sB1[D1];
    __shared__ int   s_nz;
    __shared__ int   sSteal;
    int* sScan = (int*)sT;   // overlay: scan (P2) and tile buffer (P5) are disjoint in time

    int t   = threadIdx.x;
    int blk = blockIdx.x;
    int gid = blk * NT + t;
    int w   = t >> 5, lane = t & 31;

    // ---- P0: zero histogram; block 0 detects edge dtype; reset steal[1].
    // Values in [0,50000): little-endian int64 => odd 32-bit words of the
    // first 1024 entries are all 0; int32 => they are random edge ids.
    if (gid == 0) g_steal[1] = 0;
    for (int i = gid; i < NN; i += GRID * NT) g_cnt[i] = 0;
    if (blk == 0) {
        const int* e = (const int*)ep;
        int local = 0;
#pragma unroll
        for (int q = 0; q < 4; q++) local |= e[2 * (t * 4 + q) + 1];
        if (t == 0) s_nz = 0;
        __syncthreads();
        if (local) atomicOr(&s_nz, 1);
        __syncthreads();
        if (t == 0) g_is64 = (s_nz == 0) ? 1 : 0;
    }
    gbar();
    int is64 = __ldcg(&g_is64);

    // ---- P1: in-degree histogram
    if (is64) {
        const longlong2* p = (const longlong2*)ep;
        for (int i = gid; i < NE / 2; i += GRID * NT) {
            longlong2 dd = p[NE / 2 + i];
            atomicAdd(&g_cnt[(int)dd.x], 1);
            atomicAdd(&g_cnt[(int)dd.y], 1);
        }
    } else {
        const int2* p = (const int2*)ep;
        for (int i = gid; i < NE / 2; i += GRID * NT) {
            int2 dd = p[NE / 2 + i];
            atomicAdd(&g_cnt[dd.x], 1);
            atomicAdd(&g_cnt[dd.y], 1);
        }
    }
    gbar();

    // ---- P2a: block-local inclusive scan of counts (one node per thread;
    // NN < GRID*NT so a single pass covers all nodes)
    int c = (gid < NN) ? __ldcg(&g_cnt[gid]) : 0;
    sScan[t] = c;
    __syncthreads();
#pragma unroll
    for (int off = 1; off < NT; off <<= 1) {
        int v = sScan[t];
        int a = (t >= off) ? sScan[t - off] : 0;
        __syncthreads();
        sScan[t] = v + a;
        __syncthreads();
    }
    int incl = sScan[t];
    if (t == NT - 1) g_bsum[blk] = incl;
    gbar();

    // ---- P2b: block 0 scans the GRID block totals
    if (blk == 0) {
        constexpr int PB = (GRID + NT - 1) / NT;   // 3
        int loc[PB];
        int s = 0;
#pragma unroll
        for (int q = 0; q < PB; q++) {
            int idx = t * PB + q;
            loc[q] = (idx < GRID) ? __ldcg(&g_bsum[idx]) : 0;
            s += loc[q];
        }
        sScan[t] = s;
        __syncthreads();
#pragma unroll
        for (int off = 1; off < NT; off <<= 1) {
            int v = sScan[t];
            int ad = (t >= off) ? sScan[t - off] : 0;
            __syncthreads();
            sScan[t] = v + ad;
            __syncthreads();
        }
        int run = sScan[t] - s;
#pragma unroll
        for (int q = 0; q < PB; q++) {
            int idx = t * PB + q;
            if (idx < GRID) { g_bpre[idx] = run; run += loc[q]; }
        }
    }
    gbar();

    // ---- P2c: write row/cur/dis
    if (gid < NN) {
        int base = __ldcg(&g_bpre[blk]);
        int excl = base + incl - c;
        g_row[gid] = excl;
        g_cur[gid] = excl;
        g_dis[gid] = rsqrtf((float)c + 1.0f);
    }
    if (gid == 0) g_row[NN] = NE;
    gbar();

    // ---- P3: CSR scatter
    if (is64) {
        const long long* p = (const long long*)ep;
        for (int e = gid; e < NE; e += GRID * NT) {
            int s = (int)p[e];
            int d = (int)p[NE + e];
            int pos = atomicAdd(&g_cur[d], 1);
            g_csr[pos] = s;
        }
    } else {
        const int* p = (const int*)ep;
        for (int e = gid; e < NE; e += GRID * NT) {
            int s = p[e];
            int d = p[NE + e];
            int pos = atomicAdd(&g_cur[d], 1);
            g_csr[pos] = s;
        }
    }
    gbar();

    // ---- P4: FUSED gather + double GEMM per stolen 16-row tile.
    // Per tile: each warp gathers z for its 2 nodes into sT, then the block
    // computes h = relu(zW1+b1) in smem and hs2 = (hW2)*dis to gmem. Gathers
    // of one block overlap GEMMs of its SM-neighbors (4 blocks/SM).
    {
        // stage W1, W2, b1 once per block
        for (int i = t; i < D0 * D1 / 4; i += NT)
            ((float4*)sW1)[i] = ((const float4*)W1)[i];
        for (int i = t; i < D1 * D2 / 4; i += NT)
            ((float4*)sW2)[i] = ((const float4*)W2)[i];
        if (t < D1) sB1[t] = b1[t];

        const float2* X2 = (const float2*)x;
        int rbase = w * 2;                       // 2 rows per warp
        const int ntile = NN / 16;               // 3125, exact
        for (;;) {
            __syncthreads();   // W/b staged; prior iter done with sT+sSteal
            if (t == 0) sSteal = (int)atomicAdd(&g_steal[0], 1u);
            __syncthreads();
            int tile = sSteal;
            if (tile >= ntile) break;
            int row0 = tile * 16;

            // gather z rows (warp w -> smem rows 2w, 2w+1)
            aggx_to_smem(row0 + rbase,     X2, &sT[(rbase)     * D0], lane);
            aggx_to_smem(row0 + rbase + 1, X2, &sT[(rbase + 1) * D0], lane);
            __syncthreads();

            // GEMM1: acc1[r][c] = sum_k z[r][k] * W1[k][96]
            float acc1[2][3];
#pragma unroll
            for (int r = 0; r < 2; r++)
#pragma unroll
                for (int cc = 0; cc < 3; cc++) acc1[r][cc] = 0.0f;
#pragma unroll
            for (int k = 0; k < D0; k++) {
                float wv[3];
#pragma unroll
                for (int cc = 0; cc < 3; cc++) wv[cc] = sW1[k * D1 + lane + 32 * cc];
                float xv0 = sT[(rbase)     * D0 + k];
                float xv1 = sT[(rbase + 1) * D0 + k];
#pragma unroll
                for (int cc = 0; cc < 3; cc++) {
                    acc1[0][cc] = fmaf(xv0, wv[cc], acc1[0][cc]);
                    acc1[1][cc] = fmaf(xv1, wv[cc], acc1[1][cc]);
                }
            }
            __syncthreads();   // everyone done reading z from sT

            // h = relu(acc1 + b1) -> sT as [16][96]
#pragma unroll
            for (int r = 0; r < 2; r++)
#pragma unroll
                for (int cc = 0; cc < 3; cc++)
                    sT[(rbase + r) * D1 + lane + 32 * cc] =
                        act_relu(acc1[r][cc] + sB1[lane + 32 * cc]);
            __syncthreads();   // h tile complete

            // GEMM2: acc2[r][c] = sum_k h[r][k] * W2[k][64]; scale by dis
            float acc2[2][2];
#pragma unroll
            for (int r = 0; r < 2; r++)
#pragma unroll
                for (int cc = 0; cc < 2; cc++) acc2[r][cc] = 0.0f;
#pragma unroll
            for (int k = 0; k < D1; k++) {
                float wv[2];
#pragma unroll
                for (int cc = 0; cc < 2; cc++) wv[cc] = sW2[k * D2 + lane + 32 * cc];
                float hv0 = sT[(rbase)     * D1 + k];
                float hv1 = sT[(rbase + 1) * D1 + k];
#pragma unroll
                for (int cc = 0; cc < 2; cc++) {
                    acc2[0][cc] = fmaf(hv0, wv[cc], acc2[0][cc]);
                    acc2[1][cc] = fmaf(hv1, wv[cc], acc2[1][cc]);
                }
            }
#pragma unroll
            for (int r = 0; r < 2; r++) {
                int gr = row0 + rbase + r;
                float d = g_dis[gr];
#pragma unroll
                for (int cc = 0; cc < 2; cc++)
                    g_hs2[gr * D2 + lane + 32 * cc] = acc2[r][cc] * d;
            }
        }
    }
    gbar();

    // ---- P5: layer-2 aggregation (stolen chunks of 16); reset steal[0]
    if (gid == 0) g_steal[0] = 0;
    {
        const float2* H2 = (const float2*)g_hs2;
        for (;;) {
            __syncthreads();
            if (t == 0) sSteal = (int)atomicAdd(&g_steal[1], 1u);
            __syncthreads();
            int base = sSteal * 16;
            if (base >= NN) break;
#pragma unroll
            for (int q = 0; q < 2; q++) {
                int node = base + w * 2 + q;
                if (node < NN) agg2_node(node, H2, b2, out, lane);
            }
        }
    }
}

// ---------------- launch: ONE kernel ---------------------------------------
extern "C" void kernel_launch(void* const* d_in, const int* in_sizes, int n_in,
                              void* d_out, int out_size) {
    const float* x  = (const float*)d_in[0];
    const void*  ei = d_in[1];
    const float* W1 = (const float*)d_in[2];
    const float* b1 = (const float*)d_in[3];
    const float* W2 = (const float*)d_in[4];
    const float* b2 = (const float*)d_in[5];
    float* out = (float*)d_out;

    k_fused<<<GRID, NT>>>(x, ei, W1, b1, W2, b2, out);
}

// round 17
// speedup vs baseline: 1.0746x; 1.0746x over previous
#include <cuda_runtime.h>
#include <math.h>

// Problem constants (shapes fixed by the dataset)
#define NN 50000
#define NE 800000
#define D0 64   // x features
#define D1 96   // hidden
#define D2 64   // out

#define GRID 740    // 5 blocks/SM * 148 SMs — fully balanced persistent grid
#define NT   256    // threads per block

// ---------------- scratch (device globals: no allocation allowed) ----------
__device__ int      g_is64;
__device__ int      g_csr[NE];
__device__ int      g_cnt[NN];
__device__ int      g_row[NN + 1];
__device__ int      g_cur[NN];
__device__ float    g_dis[NN];
__device__ int      g_bsum[GRID];
__device__ int      g_bpre[GRID];
__device__ unsigned g_barrier_ctr;   // monotonic across launches (replay-safe)
__device__ unsigned g_steal[4];      // work-steal: aggx, gemm1, gemm2, agg2
__device__ float    g_z  [NN * D0];  // D-hat(x): fully normalized agg of x
__device__ float    g_h  [NN * D1];  // relu(z@W1 + b1)
__device__ float    g_hs2[NN * D2];  // (h@W2)*dis[row]

__device__ __forceinline__ float act_relu(float v)    { return fmaxf(v, 0.0f); }
__device__ __forceinline__ float act_sigmoid(float v) { return 1.0f / (1.0f + expf(-v)); }

// ---------------- software grid barrier ------------------------------------
__device__ __forceinline__ void gbar() {
    __threadfence();
    __syncthreads();
    if (threadIdx.x == 0) {
        unsigned old = atomicAdd(&g_barrier_ctr, 1u);
        unsigned target = (old / GRID) * GRID + GRID;
        while ((int)(*(volatile unsigned*)&g_barrier_ctr - target) < 0)
            __nanosleep(64);
        __threadfence();
    }
    __syncthreads();
}

// ---------------- GEMM phase (R12-proven core, work-stealing 32-row tiles) --
// EPI=0: OUT = relu(acc + bias)       (layer 1: z -> h)
// EPI=1: OUT = acc * dis[row]         (layer 2: h -> hs2)
template <int IN, int OUT, int EPI>
__device__ void gemm_phase(const float* __restrict__ X, const float* __restrict__ Wm,
                           const float* __restrict__ bias, float* __restrict__ HS,
                           float* sWs, float* sXs, float* sB,
                           unsigned* ctr, volatile int* sStealP) {
    constexpr int CPL = OUT / 32;
    constexpr int K4  = IN / 4;
    int t = threadIdx.x;
    // stage W (float4) and bias once
    for (int i = t; i < IN * OUT / 4; i += NT)
        ((float4*)sWs)[i] = ((const float4*)Wm)[i];
    if (EPI == 0 && t < OUT) sB[t] = bias[t];

    int w = t >> 5, lane = t & 31;
    int rbase = w * 4;
    const int ntile = (NN + 31) / 32;

    for (;;) {
        __syncthreads();   // W staged / prior iter readers done with sXs+sSteal
        if (t == 0) *sStealP = (int)atomicAdd(ctr, 1u);
        __syncthreads();
        int tile = *sStealP;
        if (tile >= ntile) break;

        int row0 = tile * 32;
        for (int i = t; i < 32 * K4; i += NT) {
            int r = i / K4, k4 = i % K4;
            int gr = row0 + r;
            ((float4*)sXs)[i] = (gr < NN) ? ((const float4*)X)[gr * K4 + k4]
                                          : make_float4(0.f, 0.f, 0.f, 0.f);
        }
        __syncthreads();

        float acc[4][CPL];
#pragma unroll
        for (int r = 0; r < 4; r++)
#pragma unroll
            for (int c = 0; c < CPL; c++) acc[r][c] = 0.0f;

#pragma unroll
        for (int k = 0; k < IN; k++) {
            float wv[CPL];
#pragma unroll
            for (int c = 0; c < CPL; c++) wv[c] = sWs[k * OUT + lane + 32 * c];
            float xv[4];
#pragma unroll
            for (int r = 0; r < 4; r++) xv[r] = sXs[(rbase + r) * IN + k];
#pragma unroll
            for (int r = 0; r < 4; r++)
#pragma unroll
                for (int c = 0; c < CPL; c++)
                    acc[r][c] = fmaf(xv[r], wv[c], acc[r][c]);
        }

#pragma unroll
        for (int r = 0; r < 4; r++) {
            int gr = row0 + rbase + r;
            if (gr < NN) {
                if (EPI == 0) {
#pragma unroll
                    for (int c = 0; c < CPL; c++)
                        HS[gr * OUT + lane + 32 * c] =
                            act_relu(acc[r][c] + sB[lane + 32 * c]);
                } else {
                    float d = g_dis[gr];
#pragma unroll
                    for (int c = 0; c < CPL; c++)
                        HS[gr * OUT + lane + 32 * c] = acc[r][c] * d;
                }
            }
        }
    }
}

// ---------------- per-node aggregation bodies ------------------------------
// Layer-1 agg on RAW x (64f): z_i = dis_i * ( dis_i*x_i + sum_e dis_src*x_src )
__device__ __forceinline__ void aggx_node(int node, const float2* __restrict__ X2,
                                          float* __restrict__ Z, int lane) {
    constexpr int C2 = D0 / 2;   // 32, all lanes active
    int beg = g_row[node], end = g_row[node + 1];
    float di = g_dis[node];
    float2 xv = X2[node * C2 + lane];
    float2 acc = make_float2(xv.x * di, xv.y * di);   // self: dis_i * x_i

    int j = beg;
    for (; j + 4 <= end; j += 4) {
        int s0 = g_csr[j + 0], s1 = g_csr[j + 1];
        int s2 = g_csr[j + 2], s3 = g_csr[j + 3];
        float d0 = g_dis[s0], d1 = g_dis[s1], d2 = g_dis[s2], d3 = g_dis[s3];
        float2 v0 = X2[s0 * C2 + lane];
        float2 v1 = X2[s1 * C2 + lane];
        float2 v2 = X2[s2 * C2 + lane];
        float2 v3 = X2[s3 * C2 + lane];
        acc.x = fmaf(v0.x, d0, fmaf(v1.x, d1, fmaf(v2.x, d2, fmaf(v3.x, d3, acc.x))));
        acc.y = fmaf(v0.y, d0, fmaf(v1.y, d1, fmaf(v2.y, d2, fmaf(v3.y, d3, acc.y))));
    }
    for (; j < end; j++) {
        int s0 = g_csr[j];
        float d0 = g_dis[s0];
        float2 v = X2[s0 * C2 + lane];
        acc.x = fmaf(v.x, d0, acc.x);
        acc.y = fmaf(v.y, d0, acc.y);
    }
    ((float2*)Z)[node * C2 + lane] = make_float2(di * acc.x, di * acc.y);
}

// Layer-2 agg on PRE-SCALED hs2 (64f):
//   out_i = sigmoid( dis_i * ( hs2_i + sum_e hs2_src ) + b2 )
__device__ __forceinline__ void agg2_node(int node, const float2* __restrict__ H2,
                                          const float* __restrict__ b,
                                          float* __restrict__ OUT, int lane) {
    constexpr int C2 = D2 / 2;   // 32
    int beg = g_row[node], end = g_row[node + 1];
    float2 acc = H2[node * C2 + lane];
    int j = beg;
    for (; j + 4 <= end; j += 4) {
        int s0 = g_csr[j + 0], s1 = g_csr[j + 1];
        int s2 = g_csr[j + 2], s3 = g_csr[j + 3];
        float2 v0 = H2[s0 * C2 + lane];
        float2 v1 = H2[s1 * C2 + lane];
        float2 v2 = H2[s2 * C2 + lane];
        float2 v3 = H2[s3 * C2 + lane];
        acc.x += (v0.x + v1.x) + (v2.x + v3.x);
        acc.y += (v0.y + v1.y) + (v2.y + v3.y);
    }
    for (; j < end; j++) {
        int s0 = g_csr[j];
        float2 v = H2[s0 * C2 + lane];
        acc.x += v.x; acc.y += v.y;
    }
    float d = g_dis[node];
    float2 bb = ((const float2*)b)[lane];
    float2 o;
    o.x = act_sigmoid(fmaf(d, acc.x, bb.x));
    o.y = act_sigmoid(fmaf(d, acc.y, bb.y));
    ((float2*)OUT)[node * C2 + lane] = o;
}

// ---------------- the single fused persistent kernel -----------------------
// smem: sWs 24KB + sXs 12KB + scan 1KB + sB 384B -> ~37.7KB; 5 blocks/SM.
__global__ void __launch_bounds__(NT, 5)
k_fused(const float* __restrict__ x, const void* __restrict__ ep,
        const float* __restrict__ W1, const float* __restrict__ b1,
        const float* __restrict__ W2, const float* __restrict__ b2,
        float* __restrict__ out) {
    __shared__ __align__(16) float sWs[D1 * D2 > D0 * D1 ? D1 * D2 : D0 * D1];
    __shared__ __align__(16) float sXs[32 * D1];
    __shared__ float sB[D1];
    __shared__ int   sScan[NT];
    __shared__ int   s_nz;
    __shared__ int   sSteal;

    int t   = threadIdx.x;
    int blk = blockIdx.x;
    int gid = blk * NT + t;
    int w   = t >> 5, lane = t & 31;

    // ---- P0: zero histogram; block 0 detects edge dtype; reset steal[3].
    // Values in [0,50000): little-endian int64 => odd 32-bit words of the
    // first 1024 entries are all 0; int32 => they are random edge ids.
    if (gid == 0) g_steal[3] = 0;
    if (gid < NN) g_cnt[gid] = 0;
    if (blk == 0) {
        const int* e = (const int*)ep;
        int local = 0;
#pragma unroll
        for (int q = 0; q < 4; q++) local |= e[2 * (t * 4 + q) + 1];
        if (t == 0) s_nz = 0;
        __syncthreads();
        if (local) atomicOr(&s_nz, 1);
        __syncthreads();
        if (t == 0) g_is64 = (s_nz == 0) ? 1 : 0;
    }
    gbar();
    int is64 = __ldcg(&g_is64);

    // ---- P1: in-degree histogram
    if (is64) {
        const longlong2* p = (const longlong2*)ep;
        for (int i = gid; i < NE / 2; i += GRID * NT) {
            longlong2 dd = p[NE / 2 + i];
            atomicAdd(&g_cnt[(int)dd.x], 1);
            atomicAdd(&g_cnt[(int)dd.y], 1);
        }
    } else {
        const int2* p = (const int2*)ep;
        for (int i = gid; i < NE / 2; i += GRID * NT) {
            int2 dd = p[NE / 2 + i];
            atomicAdd(&g_cnt[dd.x], 1);
            atomicAdd(&g_cnt[dd.y], 1);
        }
    }
    gbar();

    // ---- P2a: block-local inclusive scan of counts (one node per thread)
    int c = (gid < NN) ? __ldcg(&g_cnt[gid]) : 0;
    sScan[t] = c;
    __syncthreads();
#pragma unroll
    for (int off = 1; off < NT; off <<= 1) {
        int v = sScan[t];
        int a = (t >= off) ? sScan[t - off] : 0;
        __syncthreads();
        sScan[t] = v + a;
        __syncthreads();
    }
    int incl = sScan[t];
    if (t == NT - 1) g_bsum[blk] = incl;
    gbar();

    // ---- P2b: block 0 scans the GRID block totals
    if (blk == 0) {
        constexpr int PB = (GRID + NT - 1) / NT;   // 3
        int loc[PB];
        int s = 0;
#pragma unroll
        for (int q = 0; q < PB; q++) {
            int idx = t * PB + q;
            loc[q] = (idx < GRID) ? __ldcg(&g_bsum[idx]) : 0;
            s += loc[q];
        }
        sScan[t] = s;
        __syncthreads();
#pragma unroll
        for (int off = 1; off < NT; off <<= 1) {
            int v = sScan[t];
            int ad = (t >= off) ? sScan[t - off] : 0;
            __syncthreads();
            sScan[t] = v + ad;
            __syncthreads();
        }
        int run = sScan[t] - s;
#pragma unroll
        for (int q = 0; q < PB; q++) {
            int idx = t * PB + q;
            if (idx < GRID) { g_bpre[idx] = run; run += loc[q]; }
        }
    }
    gbar();

    // ---- P2c: write row/cur/dis
    if (gid < NN) {
        int base = __ldcg(&g_bpre[blk]);
        int excl = base + incl - c;
        g_row[gid] = excl;
        g_cur[gid] = excl;
        g_dis[gid] = rsqrtf((float)c + 1.0f);
    }
    if (gid == 0) g_row[NN] = NE;
    gbar();

    // ---- P3: CSR scatter
    if (is64) {
        const long long* p = (const long long*)ep;
        for (int e = gid; e < NE; e += GRID * NT) {
            int s = (int)p[e];
            int d = (int)p[NE + e];
            int pos = atomicAdd(&g_cur[d], 1);
            g_csr[pos] = s;
        }
    } else {
        const int* p = (const int*)ep;
        for (int e = gid; e < NE; e += GRID * NT) {
            int s = p[e];
            int d = p[NE + e];
            int pos = atomicAdd(&g_cur[d], 1);
            g_csr[pos] = s;
        }
    }
    gbar();

    // ---- P4: aggregate RAW x -> z (64f gathers; stolen chunks of 16 nodes)
    {
        const float2* X2 = (const float2*)x;
        for (;;) {
            __syncthreads();
            if (t == 0) sSteal = (int)atomicAdd(&g_steal[0], 1u);
            __syncthreads();
            int base = sSteal * 16;
            if (base >= NN) break;
#pragma unroll
            for (int q = 0; q < 2; q++) {
                int node = base + w * 2 + q;
                if (node < NN) aggx_node(node, X2, g_z, lane);
            }
        }
    }
    gbar();

    // ---- P5: gemm1  h = relu(z@W1 + b1)   (stolen tiles); reset steal[0]
    if (gid == 0) g_steal[0] = 0;
    gemm_phase<D0, D1, 0>(g_z, W1, b1, g_h, sWs, sXs, sB, &g_steal[1], &sSteal);
    gbar();

    // ---- P6: gemm2  hs2 = (h@W2)*dis      (stolen tiles); reset steal[1]
    if (gid == 0) g_steal[1] = 0;
    gemm_phase<D1, D2, 1>(g_h, W2, b2, g_hs2, sWs, sXs, sB, &g_steal[2], &sSteal);
    gbar();

    // ---- P7: layer-2 aggregation; reset steal[2]
    if (gid == 0) g_steal[2] = 0;
    {
        const float2* H2 = (const float2*)g_hs2;
        for (;;) {
            __syncthreads();
            if (t == 0) sSteal = (int)atomicAdd(&g_steal[3], 1u);
            __syncthreads();
            int base = sSteal * 16;
            if (base >= NN) break;
#pragma unroll
            for (int q = 0; q < 2; q++) {
                int node = base + w * 2 + q;
                if (node < NN) agg2_node(node, H2, b2, out, lane);
            }
        }
    }
}

// ---------------- launch: ONE kernel ---------------------------------------
extern "C" void kernel_launch(void* const* d_in, const int* in_sizes, int n_in,
                              void* d_out, int out_size) {
    const float* x  = (const float*)d_in[0];
    const void*  ei = d_in[1];
    const float* W1 = (const float*)d_in[2];
    const float* b1 = (const float*)d_in[3];
    const float* W2 = (const float*)d_in[4];
    const float* b2 = (const float*)d_in[5];
    float* out = (float*)d_out;

    k_fused<<<GRID, NT>>>(x, ei, W1, b1, W2, b2, out);
}